// round 16
// baseline (speedup 1.0000x reference)
#include <cuda_runtime.h>
#include <cuda_fp16.h>
#include <cstdint>

#define CIN   6
#define COUT  16
#define FS    5
#define HIN   512
#define WIN   512
#define HOUT  508
#define WOUT  508
#define BATCHN 32

// ---- dense weights (fp32), built per launch ----
__device__ float g_Wd[FS * FS * CIN * COUT];

__global__ void build_weights(const float* __restrict__ w3,
                              const float* __restrict__ w4,
                              const float* __restrict__ w44,
                              const float* __restrict__ w6) {
    int idx = blockIdx.x * blockDim.x + threadIdx.x;
    if (idx >= FS * FS * CIN * COUT) return;
    int co = idx % COUT;
    int ci = (idx / COUT) % CIN;
    int kk = idx / (COUT * CIN);
    float v = 0.f;
    if (co < 6) {
        int i = co;
        #pragma unroll
        for (int m = 0; m < 3; ++m)
            if (ci == (i + m) % 6) v = w3[(kk * 3 + m) * 6 + i];
    } else if (co < 12) {
        int k = co - 6;
        #pragma unroll
        for (int m = 0; m < 4; ++m)
            if (ci == (k + m) % 6) v = w4[(kk * 4 + m) * 6 + k];
    } else if (co < 15) {
        int k = co - 12;
        const int off[4] = {0, 1, 3, 4};
        #pragma unroll
        for (int m = 0; m < 4; ++m)
            if (ci == (k + off[m]) % 6) v = w44[(kk * 4 + m) * 3 + k];
    } else {
        v = w6[kk * 6 + ci];
    }
    g_Wd[idx] = v;
}

// ===== fp16 mma m16n8k16 conv, permuted m/n, coalesced staging =====
// m-row g ↦ co 2g ; m-row g+8 ↦ co 2g+1 ; n-col c ↦ px (c>>1)+4(c&1).
// K 0..7 = pixel kx=2p {ci0..ci5, bias(1.0), 0}; K 8..15 = kx=2p+1.
// Weight K6 = bias[co] only on tap-pair (ky=2, p=1).
// Staging: thread t owns (pixel t/3, word t%3) -> linear LDG.64 + STS.32.
// Word3 {1.0, 0} filled by a separate constant pass.

#define TW    64
#define RT    16            // 8 warps x 2 rows
#define AROWS (RT + 4)      // 20
#define ACOLS (TW + 5)      // 69

#define H2_ONE0 0x00003C00u   // h2(1.0f, 0.0f)

__device__ __forceinline__ uint32_t h2(float a, float b) {
    __half2 h = __floats2half2_rn(a, b);
    return *(uint32_t*)&h;
}

__device__ __forceinline__ void mma_f16(float d[4],
                                        uint32_t a0, uint32_t a1,
                                        uint32_t a2, uint32_t a3,
                                        uint32_t b0, uint32_t b1) {
    asm volatile(
        "mma.sync.aligned.m16n8k16.row.col.f32.f16.f16.f32 "
        "{%0,%1,%2,%3}, {%4,%5,%6,%7}, {%8,%9}, {%0,%1,%2,%3};"
        : "+f"(d[0]), "+f"(d[1]), "+f"(d[2]), "+f"(d[3])
        : "r"(a0), "r"(a1), "r"(a2), "r"(a3), "r"(b0), "r"(b1));
}

__global__ __launch_bounds__(256, 2) void conv_mma_kernel(
    const float* __restrict__ in,
    const float* __restrict__ bias,
    float* __restrict__ out) {

    __shared__ uint4 s_in[AROWS][ACOLS];        // 22080 B
    __shared__ uint4 s_w[15][8][4];             // 7680 B

    const int tid = threadIdx.x;
    const int b  = blockIdx.z;
    const int y0 = blockIdx.y * RT;
    const int x0 = blockIdx.x * TW;

    uint32_t* s_u32 = (uint32_t*)&s_in[0][0];

    // ---- weight staging: 480 uint4 entries; m-row -> co permuted ----
    for (int e = tid; e < 15 * 8 * 4; e += 256) {
        const int kp  = e >> 5;          // tap pair: ky*3 + p
        const int gg  = (e >> 2) & 7;
        const int tqq = e & 3;
        const int ky  = kp / 3;
        const int p   = kp - 3 * ky;
        float wv[2][4];
        #pragma unroll
        for (int j = 0; j < 4; ++j) {
            const int K    = 2 * tqq + (j & 1) + (j >> 1) * 8;
            const int half = K >> 3;
            const int s    = K & 7;
            const int kx   = 2 * p + half;
            #pragma unroll
            for (int h = 0; h < 2; ++h) {
                const int co = 2 * gg + h;   // m-row g -> co 2g, g+8 -> 2g+1
                float v = 0.f;
                if (kx <= 4) {
                    if (s < 6)
                        v = g_Wd[((ky * 5 + kx) * 6 + s) * COUT + co];
                    else if (s == 6 && half == 0 && ky == 2 && p == 1)
                        v = bias[co];
                }
                wv[h][j] = v;
            }
        }
        s_w[kp][gg][tqq] = make_uint4(h2(wv[0][0], wv[0][1]),
                                      h2(wv[1][0], wv[1][1]),
                                      h2(wv[0][2], wv[0][3]),
                                      h2(wv[1][2], wv[1][3]));
    }

    // ---- constant word3 pass: {1.0, 0} per pixel ----
    for (int i = tid; i < AROWS * ACOLS; i += 256)
        s_u32[i * 4 + 3] = H2_ONE0;

    // ---- coalesced input staging: thread t = (pixel t/3, word t%3) ----
    if (tid < 3 * ACOLS) {                 // 207 threads
        const int c = tid / 3;             // computed once
        const int w = tid - 3 * c;
        const int gx = x0 + c;
        const bool xok = gx < WIN;
        const float* ipb = in + ((long long)(b * HIN + y0) * WIN + gx) * CIN + 2 * w;
        uint32_t* sp = s_u32 + c * 4 + w;
        #pragma unroll 4
        for (int r = 0; r < AROWS; ++r) {
            float2 v = make_float2(0.f, 0.f);
            if (xok && (y0 + r) < HIN)
                v = *(const float2*)(ipb + (long long)r * (WIN * CIN));
            sp[r * (ACOLS * 4)] = h2(v.x, v.y);
        }
    }
    __syncthreads();

    // ---- per-warp MMA mainloop: 2 output rows, pair-outer (R15) ----
    const int w    = tid >> 5;
    const int lane = tid & 31;
    const int g    = lane >> 2;
    const int tq   = lane & 3;
    const int r0   = 2 * w;
    const int pxg  = (g >> 1) + 4 * (g & 1);   // n-col -> px offset

    float d[2][8][4];
    #pragma unroll
    for (int rr = 0; rr < 2; ++rr)
        #pragma unroll
        for (int n = 0; n < 8; ++n)
            #pragma unroll
            for (int q = 0; q < 4; ++q) d[rr][n][q] = 0.f;

    uint4 aBuf[2][3];
    const uint32_t* s_inf = (const uint32_t*)&s_in[0][0];

    #pragma unroll
    for (int sr = 0; sr < 6; ++sr) {
        const int cur = sr & 1;
        const int prv = cur ^ 1;
        if (sr <= 4) {
            #pragma unroll
            for (int p = 0; p < 3; ++p)
                aBuf[cur][p] = s_w[sr * 3 + p][g][tq];
        }
        const uint32_t* brow = s_inf + ((r0 + sr) * ACOLS + pxg) * 4 + tq;
        #pragma unroll
        for (int p = 0; p < 3; ++p) {
            const uint4 aC = aBuf[cur][p];
            const uint4 aP = aBuf[prv][p];
            #pragma unroll
            for (int n = 0; n < 8; ++n) {
                const uint32_t* bp = brow + (n * 8 + 2 * p) * 4;
                uint32_t b0 = bp[0];     // pixel kx=2p
                uint32_t b1 = bp[4];     // pixel kx=2p+1
                if (sr <= 4)
                    mma_f16(d[0][n], aC.x, aC.y, aC.z, aC.w, b0, b1);
                if (sr >= 1)
                    mma_f16(d[1][n], aP.x, aP.y, aP.z, aP.w, b0, b1);
            }
        }
    }

    // ---- epilogue: coalesced float2 stores (co pairs, consecutive px) ----
    #pragma unroll
    for (int rr = 0; rr < 2; ++rr) {
        const int gy = y0 + r0 + rr;
        if (gy < HOUT) {
            float* orow = out + ((long long)(b * HOUT + gy) * WOUT) * COUT;
            #pragma unroll
            for (int n = 0; n < 8; ++n) {
                int pxA = x0 + n * 8 + tq;
                int pxB = pxA + 4;
                if (pxA < WOUT)
                    *(float2*)(orow + (long long)pxA * COUT + 2 * g) =
                        make_float2(d[rr][n][0], d[rr][n][2]);
                if (pxB < WOUT)
                    *(float2*)(orow + (long long)pxB * COUT + 2 * g) =
                        make_float2(d[rr][n][1], d[rr][n][3]);
            }
        }
    }
}

extern "C" void kernel_launch(void* const* d_in, const int* in_sizes, int n_in,
                              void* d_out, int out_size) {
    const float* inputs = (const float*)d_in[0];
    const float* w3     = (const float*)d_in[1];
    const float* w4     = (const float*)d_in[2];
    const float* w44    = (const float*)d_in[3];
    const float* w6     = (const float*)d_in[4];
    const float* bias   = (const float*)d_in[5];

    build_weights<<<(FS * FS * CIN * COUT + 255) / 256, 256>>>(w3, w4, w44, w6);

    dim3 grid((WOUT + TW - 1) / TW,   // 8
              (HOUT + RT - 1) / RT,   // 32
              BATCHN);                 // 32
    conv_mma_kernel<<<grid, 256>>>(inputs, bias, (float*)d_out);
}

// round 17
// speedup vs baseline: 1.3144x; 1.3144x over previous
#include <cuda_runtime.h>
#include <cuda_fp16.h>
#include <cstdint>

#define CIN   6
#define COUT  16
#define FS    5
#define HIN   512
#define WIN   512
#define HOUT  508
#define WOUT  508
#define BATCHN 32

// ---- dense weights (fp32), built per launch ----
__device__ float g_Wd[FS * FS * CIN * COUT];

__global__ void build_weights(const float* __restrict__ w3,
                              const float* __restrict__ w4,
                              const float* __restrict__ w44,
                              const float* __restrict__ w6) {
    int idx = blockIdx.x * blockDim.x + threadIdx.x;
    if (idx >= FS * FS * CIN * COUT) return;
    int co = idx % COUT;
    int ci = (idx / COUT) % CIN;
    int kk = idx / (COUT * CIN);
    float v = 0.f;
    if (co < 6) {
        int i = co;
        #pragma unroll
        for (int m = 0; m < 3; ++m)
            if (ci == (i + m) % 6) v = w3[(kk * 3 + m) * 6 + i];
    } else if (co < 12) {
        int k = co - 6;
        #pragma unroll
        for (int m = 0; m < 4; ++m)
            if (ci == (k + m) % 6) v = w4[(kk * 4 + m) * 6 + k];
    } else if (co < 15) {
        int k = co - 12;
        const int off[4] = {0, 1, 3, 4};
        #pragma unroll
        for (int m = 0; m < 4; ++m)
            if (ci == (k + off[m]) % 6) v = w44[(kk * 4 + m) * 3 + k];
    } else {
        v = w6[kk * 6 + ci];
    }
    g_Wd[idx] = v;
}

// ===== fp16 mma m16n8k16, dense K-packing: 2 MMAs per ky row =====
// MMA0 K0..15 = [kx0·ci0-5 | kx1·ci0-5 | kx2·ci0-3]
// MMA1 K0..15 = [kx2·ci4-5 | kx3·ci0-5 | kx4·ci0-5 | bias(1.0) | 0]
// Pixel in smem = uint4{h2(ci0,ci1),h2(ci2,ci3),h2(ci4,ci5),h2(1,0)}.
// B fragment u32 flat offsets (u32 units from base pixel), lane tq:
//   MMA0 b0 {0,1,2,4}  b1 {5,6,8,9}
//   MMA1 b0 {10,12,13,14} b1 {16,17,18,19}  (19 = px+4 word3 = {1,0})
// m-row g ↦ co 2g, g+8 ↦ co 2g+1 ; n-col c ↦ px (c>>1)+4(c&1).
// Weight K14 of MMA1 = bias[co] on ky=2 only.

#define TW    64
#define RT    16            // 8 warps x 2 rows
#define AROWS (RT + 4)      // 20
#define ACOLS (TW + 5)      // 69

__device__ __forceinline__ uint32_t h2(float a, float b) {
    __half2 h = __floats2half2_rn(a, b);
    return *(uint32_t*)&h;
}

__device__ __forceinline__ void mma_f16(float d[4],
                                        uint32_t a0, uint32_t a1,
                                        uint32_t a2, uint32_t a3,
                                        uint32_t b0, uint32_t b1) {
    asm volatile(
        "mma.sync.aligned.m16n8k16.row.col.f32.f16.f16.f32 "
        "{%0,%1,%2,%3}, {%4,%5,%6,%7}, {%8,%9}, {%0,%1,%2,%3};"
        : "+f"(d[0]), "+f"(d[1]), "+f"(d[2]), "+f"(d[3])
        : "r"(a0), "r"(a1), "r"(a2), "r"(a3), "r"(b0), "r"(b1));
}

__global__ __launch_bounds__(256, 2) void conv_mma_kernel(
    const float* __restrict__ in,
    const float* __restrict__ bias,
    float* __restrict__ out) {

    __shared__ uint4 s_in[AROWS][ACOLS];        // 22080 B
    __shared__ uint4 s_w[5][2][8][4];           // 5120 B

    const int tid = threadIdx.x;
    const int b  = blockIdx.z;
    const int y0 = blockIdx.y * RT;
    const int x0 = blockIdx.x * TW;

    // ---- weight staging: 320 uint4 entries; dense K map ----
    for (int e = tid; e < 5 * 2 * 8 * 4; e += 256) {
        const int ky  = e >> 6;
        const int q   = (e >> 5) & 1;
        const int gg  = (e >> 2) & 7;
        const int tqq = e & 3;
        float wv[2][4];   // [m half][{K 2tqq, 2tqq+1, 2tqq+8, 2tqq+9}]
        #pragma unroll
        for (int j = 0; j < 4; ++j) {
            const int K = 2 * tqq + (j & 1) + (j >> 1) * 8;
            int kx, ci;
            if (q == 0) {
                if (K < 6)       { kx = 0; ci = K; }
                else if (K < 12) { kx = 1; ci = K - 6; }
                else             { kx = 2; ci = K - 12; }
            } else {
                if (K < 2)       { kx = 2; ci = K + 4; }
                else if (K < 8)  { kx = 3; ci = K - 2; }
                else if (K < 14) { kx = 4; ci = K - 8; }
                else             { kx = -1; ci = 0; }
            }
            #pragma unroll
            for (int h = 0; h < 2; ++h) {
                const int co = 2 * gg + h;   // m-row g -> co 2g, g+8 -> 2g+1
                float v = 0.f;
                if (kx >= 0)
                    v = g_Wd[((ky * 5 + kx) * 6 + ci) * COUT + co];
                else if (K == 14 && ky == 2)
                    v = bias[co];
                wv[h][j] = v;
            }
        }
        s_w[ky][q][gg][tqq] = make_uint4(h2(wv[0][0], wv[0][1]),
                                         h2(wv[1][0], wv[1][1]),
                                         h2(wv[0][2], wv[0][3]),
                                         h2(wv[1][2], wv[1][3]));
    }

    // ---- input staging (R15 pattern): 1x STS.128 per pixel ----
    {
        const int c  = tid & 63;
        const int rg = tid >> 6;
        const int gx = x0 + c;
        const bool xok = gx < WIN;
        #pragma unroll
        for (int k = 0; k < 5; ++k) {
            const int r  = rg + 4 * k;
            const int gy = y0 + r;
            float2 v0 = make_float2(0.f, 0.f), v1 = v0, v2 = v0;
            if (xok && gy < HIN) {
                const float* ip = in + ((long long)(b * HIN + gy) * WIN + gx) * CIN;
                v0 = *(const float2*)(ip);
                v1 = *(const float2*)(ip + 2);
                v2 = *(const float2*)(ip + 4);
            }
            s_in[r][c] = make_uint4(h2(v0.x, v0.y), h2(v1.x, v1.y),
                                    h2(v2.x, v2.y), h2(1.f, 0.f));
        }
    }
    // halo cols 64..68: threads 0..99
    if (tid < 100) {
        const int c  = 64 + tid / 20;
        const int r  = tid - 20 * (tid / 20);
        const int gx = x0 + c;
        const int gy = y0 + r;
        float2 v0 = make_float2(0.f, 0.f), v1 = v0, v2 = v0;
        if (gx < WIN && gy < HIN) {
            const float* ip = in + ((long long)(b * HIN + gy) * WIN + gx) * CIN;
            v0 = *(const float2*)(ip);
            v1 = *(const float2*)(ip + 2);
            v2 = *(const float2*)(ip + 4);
        }
        s_in[r][c] = make_uint4(h2(v0.x, v0.y), h2(v1.x, v1.y),
                                h2(v2.x, v2.y), h2(1.f, 0.f));
    }
    __syncthreads();

    // ---- per-warp MMA mainloop: 2 output rows, dense-K, pair-outer ----
    const int w    = tid >> 5;
    const int lane = tid & 31;
    const int g    = lane >> 2;
    const int tq   = lane & 3;
    const int r0   = 2 * w;
    const int pxg  = (g >> 1) + 4 * (g & 1);   // n-col -> px offset

    // lane-constant B offsets (u32 units from base pixel)
    const int off0 = (tq == 3) ? 4 : tq;          // {0,1,2,4}
    const int off1 = (tq >= 2) ? tq + 6 : tq + 5; // {5,6,8,9}
    const int off2 = (tq == 0) ? 10 : tq + 11;    // {10,12,13,14}
    const int off3 = tq + 16;                      // {16,17,18,19}

    float d[2][8][4];
    #pragma unroll
    for (int rr = 0; rr < 2; ++rr)
        #pragma unroll
        for (int n = 0; n < 8; ++n)
            #pragma unroll
            for (int q = 0; q < 4; ++q) d[rr][n][q] = 0.f;

    uint4 aBuf[2][2];
    const uint32_t* s_inf = (const uint32_t*)&s_in[0][0];

    #pragma unroll
    for (int sr = 0; sr < 6; ++sr) {
        const int cur = sr & 1;
        const int prv = cur ^ 1;
        if (sr <= 4) {
            aBuf[cur][0] = s_w[sr][0][g][tq];
            aBuf[cur][1] = s_w[sr][1][g][tq];
        }
        const uint32_t* brow = s_inf + ((r0 + sr) * ACOLS + pxg) * 4;
        const uint4 aC0 = aBuf[cur][0], aC1 = aBuf[cur][1];
        const uint4 aP0 = aBuf[prv][0], aP1 = aBuf[prv][1];
        #pragma unroll
        for (int n = 0; n < 8; ++n) {
            const uint32_t* bp = brow + n * 32;
            uint32_t b00 = bp[off0];
            uint32_t b01 = bp[off1];
            uint32_t b10 = bp[off2];
            uint32_t b11 = bp[off3];
            if (sr <= 4) {   // row0, ky = sr
                mma_f16(d[0][n], aC0.x, aC0.y, aC0.z, aC0.w, b00, b01);
                mma_f16(d[0][n], aC1.x, aC1.y, aC1.z, aC1.w, b10, b11);
            }
            if (sr >= 1) {   // row1, ky = sr-1
                mma_f16(d[1][n], aP0.x, aP0.y, aP0.z, aP0.w, b00, b01);
                mma_f16(d[1][n], aP1.x, aP1.y, aP1.z, aP1.w, b10, b11);
            }
        }
    }

    // ---- epilogue: coalesced float2 stores (co pairs, consecutive px) ----
    #pragma unroll
    for (int rr = 0; rr < 2; ++rr) {
        const int gy = y0 + r0 + rr;
        if (gy < HOUT) {
            float* orow = out + ((long long)(b * HOUT + gy) * WOUT) * COUT;
            #pragma unroll
            for (int n = 0; n < 8; ++n) {
                int pxA = x0 + n * 8 + tq;
                int pxB = pxA + 4;
                if (pxA < WOUT)
                    *(float2*)(orow + (long long)pxA * COUT + 2 * g) =
                        make_float2(d[rr][n][0], d[rr][n][2]);
                if (pxB < WOUT)
                    *(float2*)(orow + (long long)pxB * COUT + 2 * g) =
                        make_float2(d[rr][n][1], d[rr][n][3]);
            }
        }
    }
}

extern "C" void kernel_launch(void* const* d_in, const int* in_sizes, int n_in,
                              void* d_out, int out_size) {
    const float* inputs = (const float*)d_in[0];
    const float* w3     = (const float*)d_in[1];
    const float* w4     = (const float*)d_in[2];
    const float* w44    = (const float*)d_in[3];
    const float* w6     = (const float*)d_in[4];
    const float* bias   = (const float*)d_in[5];

    build_weights<<<(FS * FS * CIN * COUT + 255) / 256, 256>>>(w3, w4, w44, w6);

    dim3 grid((WOUT + TW - 1) / TW,   // 8
              (HOUT + RT - 1) / RT,   // 32
              BATCHN);                 // 32
    conv_mma_kernel<<<grid, 256>>>(inputs, bias, (float*)d_out);
}